// round 5
// baseline (speedup 1.0000x reference)
#include <cuda_runtime.h>

#define NB 2
#define NN 8192
#define NP (NB*NN)      // 16384 points total
#define HH 64
#define KK 16

// ---------------- scratch (device globals; no allocation allowed) ----------------
__device__ float g_Wall[64*192];      // folded [i][c]: c 0-63 -> q, 64-127 -> k, 128-191 -> v
__device__ float g_call[192];         // folded biases
__device__ float g_X[NP*192];         // per-point q|k|v, row stride 192
__device__ float g_A[NP*64];          // per-point xyzp @ Wp1 (no bias)
__device__ int   g_idx[NP*KK];        // global neighbor row indices

__device__ __forceinline__ float finf() { return __int_as_float(0x7f800000); }

// ================= fold: Mq=Wk@Wq etc, cq=bk@Wq etc =================
__global__ void fold_kernel(const float* __restrict__ Wk, const float* __restrict__ bk,
                            const float* __restrict__ Wq, const float* __restrict__ Wks,
                            const float* __restrict__ Wv) {
    int tid = threadIdx.x;
    for (int e = tid; e < 4096; e += blockDim.x) {
        int i = e >> 6, h = e & 63;
        float sq = 0.f, sk = 0.f, sv = 0.f;
        #pragma unroll 4
        for (int k = 0; k < 64; k++) {
            float wk = Wk[i*64 + k];
            sq = fmaf(wk, Wq [k*64 + h], sq);
            sk = fmaf(wk, Wks[k*64 + h], sk);
            sv = fmaf(wk, Wv [k*64 + h], sv);
        }
        g_Wall[i*192 + h]        = sq;
        g_Wall[i*192 + 64 + h]   = sk;
        g_Wall[i*192 + 128 + h]  = sv;
    }
    if (tid < 192) {
        int sec = tid >> 6, h = tid & 63;
        const float* W = (sec == 0) ? Wq : ((sec == 1) ? Wks : Wv);
        float s = 0.f;
        #pragma unroll 4
        for (int k = 0; k < 64; k++) s = fmaf(bk[k], W[k*64 + h], s);
        g_call[tid] = s;
    }
}

// ================= transform: g_X = F @ Wall + call ; g_A = xyzp @ Wp1 =================
struct SmemT {
    float feat[16*65];     // padded rows
    float W[64*192];
    float c[192];
    float Wp1[4*64];
};

__global__ __launch_bounds__(192) void transform_kernel(
    const float* __restrict__ features, const float* __restrict__ xyzp,
    const float* __restrict__ Wp1) {
    extern __shared__ char smem_raw[];
    SmemT* sm = (SmemT*)smem_raw;
    int tid = threadIdx.x;            // 192 threads
    int base = blockIdx.x * 16;       // 16 rows per block

    for (int i4 = tid; i4 < 64*192/4; i4 += 192)
        ((float4*)sm->W)[i4] = ((const float4*)g_Wall)[i4];
    if (tid < 192) sm->c[tid] = g_call[tid];
    if (tid < 64)  ((float4*)sm->Wp1)[tid] = ((const float4*)Wp1)[tid];
    for (int i4 = tid; i4 < 16*64/4; i4 += 192) {
        int r = i4 >> 4, cc = i4 & 15;
        float4 v = ((const float4*)(features + (size_t)(base + r)*64))[cc];
        float* d = sm->feat + r*65 + cc*4;
        d[0] = v.x; d[1] = v.y; d[2] = v.z; d[3] = v.w;
    }
    __syncthreads();

    int rg = tid / 24;   // 0..7  -> rows rg*2 + {0,1}
    int cg = tid % 24;   // 0..23 -> cols cg*8 .. +7
    float acc[2][8];
    #pragma unroll
    for (int r = 0; r < 2; r++)
        #pragma unroll
        for (int c = 0; c < 8; c++) acc[r][c] = 0.f;

    #pragma unroll 4
    for (int i = 0; i < 64; i++) {
        float x0 = sm->feat[(rg*2    )*65 + i];
        float x1 = sm->feat[(rg*2 + 1)*65 + i];
        float4 w0 = *(const float4*)(sm->W + i*192 + cg*8);
        float4 w1 = *(const float4*)(sm->W + i*192 + cg*8 + 4);
        float wv[8] = {w0.x, w0.y, w0.z, w0.w, w1.x, w1.y, w1.z, w1.w};
        #pragma unroll
        for (int c = 0; c < 8; c++) {
            acc[0][c] = fmaf(x0, wv[c], acc[0][c]);
            acc[1][c] = fmaf(x1, wv[c], acc[1][c]);
        }
    }
    #pragma unroll
    for (int r = 0; r < 2; r++) {
        int row = base + rg*2 + r;
        float4 o0, o1;
        o0.x = acc[r][0] + sm->c[cg*8 + 0];
        o0.y = acc[r][1] + sm->c[cg*8 + 1];
        o0.z = acc[r][2] + sm->c[cg*8 + 2];
        o0.w = acc[r][3] + sm->c[cg*8 + 3];
        o1.x = acc[r][4] + sm->c[cg*8 + 4];
        o1.y = acc[r][5] + sm->c[cg*8 + 5];
        o1.z = acc[r][6] + sm->c[cg*8 + 6];
        o1.w = acc[r][7] + sm->c[cg*8 + 7];
        *(float4*)(g_X + (size_t)row*192 + cg*8)     = o0;
        *(float4*)(g_X + (size_t)row*192 + cg*8 + 4) = o1;
    }

    // A = xyzp(4) @ Wp1 (bias bp1 folded in later, per query point)
    for (int o = tid; o < 16*64; o += 192) {
        int r = o >> 6, h = o & 63;
        const float* xp = xyzp + (size_t)(base + r)*4;
        float a = xp[0] * sm->Wp1[0*64 + h];
        a = fmaf(xp[1], sm->Wp1[1*64 + h], a);
        a = fmaf(xp[2], sm->Wp1[2*64 + h], a);
        a = fmaf(xp[3], sm->Wp1[3*64 + h], a);
        g_A[(size_t)(base + r)*64 + h] = a;
    }
}

// ================= knn: brute force top-16 smallest distance (set-exact) =================
__global__ __launch_bounds__(128) void knn_kernel(const float* __restrict__ xyzp) {
    __shared__ float4 sT[1024];
    int tid = threadIdx.x;                         // 128
    int b = blockIdx.x >> 6;                       // 64 blocks per batch
    int n = ((blockIdx.x & 63) << 7) + tid;
    int row = b*NN + n;
    float4 me = ((const float4*)xyzp)[row];
    float xn = me.x, yn = me.y, zn = me.z;

    float bestk[16];
    int   besti[16];
    #pragma unroll
    for (int s = 0; s < 16; s++) { bestk[s] = finf(); besti[s] = 0; }
    float wmax = finf();
    int   wpos = 0;

    for (int t = 0; t < 8; t++) {
        int tb = t * 1024;
        #pragma unroll
        for (int k = 0; k < 8; k++) {
            int m = (k << 7) + tid;
            float4 p = ((const float4*)xyzp)[b*NN + tb + m];
            p.w = fmaf(p.x, p.x, fmaf(p.y, p.y, p.z*p.z)); // |xyz|^2
            sT[m] = p;
        }
        __syncthreads();
        #pragma unroll 4
        for (int m = 0; m < 1024; m++) {
            float4 c = sT[m];
            float dot = fmaf(xn, c.x, fmaf(yn, c.y, zn*c.z));
            float key = fmaf(-2.f, dot, c.w);   // = d - sq[n]: same ordering as reference d
            if (key < wmax) {
                int gm = tb + m;
                // replace current worst (constant-index predicated moves, stays in regs)
                #pragma unroll
                for (int s = 0; s < 16; s++)
                    if (s == wpos) { bestk[s] = key; besti[s] = gm; }
                // rescan for new worst
                wmax = bestk[0]; wpos = 0;
                #pragma unroll
                for (int s = 1; s < 16; s++)
                    if (bestk[s] > wmax) { wmax = bestk[s]; wpos = s; }
            }
        }
        __syncthreads();
    }
    #pragma unroll
    for (int s = 0; s < 16; s++)
        g_idx[(size_t)row*16 + s] = b*NN + besti[s];
}

// ================= fused attention =================
struct SmemA {
    float Wp2[4096], Wt1[4096], Wt2[4096], Wa[4096];
    float bp2[64], bt1[64], bt2[64], ba[64];
    float U[128*65];     // stage buffer (padded rows)
    float Y[128*65];
    float PE[128*65];
    float Q[8*64];
    float An[8*64];      // A[n] + bp1
    float Res[8*64];
    int   Idx[128];
};

__device__ __forceinline__ void gemm8x8(const float* __restrict__ X, const float* __restrict__ W,
                                        int pg, int hg, float acc[8][8]) {
    #pragma unroll
    for (int r = 0; r < 8; r++)
        #pragma unroll
        for (int c = 0; c < 8; c++) acc[r][c] = 0.f;
    const float* xr = X + pg*8*65;
    const float* wb = W + hg*8;
    #pragma unroll 4
    for (int i = 0; i < 64; i++) {
        float x[8];
        #pragma unroll
        for (int r = 0; r < 8; r++) x[r] = xr[r*65 + i];
        float4 w0 = *(const float4*)(wb + i*64);
        float4 w1 = *(const float4*)(wb + i*64 + 4);
        float wv[8] = {w0.x, w0.y, w0.z, w0.w, w1.x, w1.y, w1.z, w1.w};
        #pragma unroll
        for (int r = 0; r < 8; r++)
            #pragma unroll
            for (int c = 0; c < 8; c++)
                acc[r][c] = fmaf(x[r], wv[c], acc[r][c]);
    }
}

__global__ __launch_bounds__(128, 1) void attn_kernel(
    const float* __restrict__ features,
    const float* __restrict__ bp1,
    const float* __restrict__ Wp2, const float* __restrict__ bp2,
    const float* __restrict__ Wt1, const float* __restrict__ bt1,
    const float* __restrict__ Wt2, const float* __restrict__ bt2,
    const float* __restrict__ Wa,  const float* __restrict__ ba,
    float* __restrict__ out) {
    extern __shared__ char smem_raw[];
    SmemA* sm = (SmemA*)smem_raw;
    int tid = threadIdx.x;      // 128
    int base = blockIdx.x * 8;  // 8 points / block, grid = NP/8

    // ---- weights + biases into smem ----
    for (int i = tid; i < 1024; i += 128) {
        ((float4*)sm->Wp2)[i] = ((const float4*)Wp2)[i];
        ((float4*)sm->Wt1)[i] = ((const float4*)Wt1)[i];
        ((float4*)sm->Wt2)[i] = ((const float4*)Wt2)[i];
        ((float4*)sm->Wa )[i] = ((const float4*)Wa )[i];
    }
    if (tid < 64) {
        sm->bp2[tid] = bp2[tid]; sm->bt1[tid] = bt1[tid];
        sm->bt2[tid] = bt2[tid]; sm->ba [tid] = ba [tid];
    }
    // ---- phase 1a: per-point data (bp1 read from gmem to avoid intra-phase hazard) ----
    {
        sm->Idx[tid] = g_idx[(size_t)base*16 + tid];
        int p = tid >> 4, c4 = tid & 15;
        int row = base + p;
        float4 q4 = *(const float4*)(g_X + (size_t)row*192 + c4*4);
        ((float4*)(sm->Q + p*64))[c4] = q4;
        float4 a4 = *(const float4*)(g_A + (size_t)row*64 + c4*4);
        float4 b4 = *(const float4*)(bp1 + c4*4);
        a4.x += b4.x; a4.y += b4.y; a4.z += b4.z; a4.w += b4.w;
        ((float4*)(sm->An + p*64))[c4] = a4;
    }
    __syncthreads();

    // ---- phase 1b: U[pair][i] = relu(An[p][i] - A_j[i]) ----
    #pragma unroll
    for (int it = 0; it < 16; it++) {
        int flat = it*128 + tid;
        int pair = flat >> 4, c4 = flat & 15;
        int g = sm->Idx[pair];
        float4 aj = *(const float4*)(g_A + (size_t)g*64 + c4*4);
        const float* an = sm->An + (pair >> 4)*64 + c4*4;
        float* up = sm->U + pair*65 + c4*4;
        up[0] = fmaxf(an[0] - aj.x, 0.f);
        up[1] = fmaxf(an[1] - aj.y, 0.f);
        up[2] = fmaxf(an[2] - aj.z, 0.f);
        up[3] = fmaxf(an[3] - aj.w, 0.f);
    }
    __syncthreads();

    int pg = tid >> 3, hg = tid & 7;  // 16 pair-groups x 8 h-groups
    float acc[8][8];

    // ---- GEMM1: PE = U @ Wp2 + bp2 ; Y(a_in) = Q - k + PE ----
    gemm8x8(sm->U, sm->Wp2, pg, hg, acc);
    #pragma unroll
    for (int r = 0; r < 8; r++) {
        int pair = pg*8 + r;
        int p = pair >> 4;
        int g = sm->Idx[pair];
        float4 k0 = *(const float4*)(g_X + (size_t)g*192 + 64 + hg*8);
        float4 k1 = *(const float4*)(g_X + (size_t)g*192 + 64 + hg*8 + 4);
        float kf[8] = {k0.x, k0.y, k0.z, k0.w, k1.x, k1.y, k1.z, k1.w};
        #pragma unroll
        for (int c = 0; c < 8; c++) {
            int col = hg*8 + c;
            float pe = acc[r][c] + sm->bp2[col];
            sm->PE[pair*65 + col] = pe;
            sm->Y [pair*65 + col] = sm->Q[p*64 + col] - kf[c] + pe;
        }
    }
    __syncthreads();

    // ---- GEMM2: U = relu(Y @ Wt1 + bt1) ----
    gemm8x8(sm->Y, sm->Wt1, pg, hg, acc);
    #pragma unroll
    for (int r = 0; r < 8; r++) {
        int pair = pg*8 + r;
        #pragma unroll
        for (int c = 0; c < 8; c++) {
            int col = hg*8 + c;
            sm->U[pair*65 + col] = fmaxf(acc[r][c] + sm->bt1[col], 0.f);
        }
    }
    __syncthreads();

    // ---- GEMM3: Y = (U @ Wt2 + bt2) / 8 ----
    gemm8x8(sm->U, sm->Wt2, pg, hg, acc);
    #pragma unroll
    for (int r = 0; r < 8; r++) {
        int pair = pg*8 + r;
        #pragma unroll
        for (int c = 0; c < 8; c++) {
            int col = hg*8 + c;
            sm->Y[pair*65 + col] = (acc[r][c] + sm->bt2[col]) * 0.125f;
        }
    }
    __syncthreads();

    // ---- softmax over j (thread-local) + weighted sum with (v + PE) ----
    {
        int p  = tid >> 4;
        int h0 = (tid & 15) << 2;
        int pbase = p * 16;
        float m0 = -finf(), m1 = -finf(), m2 = -finf(), m3 = -finf();
        #pragma unroll
        for (int j = 0; j < 16; j++) {
            const float* tr = sm->Y + (pbase + j)*65 + h0;
            m0 = fmaxf(m0, tr[0]); m1 = fmaxf(m1, tr[1]);
            m2 = fmaxf(m2, tr[2]); m3 = fmaxf(m3, tr[3]);
        }
        float n0 = 0.f, n1 = 0.f, n2 = 0.f, n3 = 0.f;
        float d0 = 0.f, d1 = 0.f, d2 = 0.f, d3 = 0.f;
        #pragma unroll
        for (int j = 0; j < 16; j++) {
            int pr = pbase + j;
            const float* tr = sm->Y + pr*65 + h0;
            float e0 = __expf(tr[0] - m0);
            float e1 = __expf(tr[1] - m1);
            float e2 = __expf(tr[2] - m2);
            float e3 = __expf(tr[3] - m3);
            d0 += e0; d1 += e1; d2 += e2; d3 += e3;
            int g = sm->Idx[pr];
            float4 v4 = *(const float4*)(g_X + (size_t)g*192 + 128 + h0);
            const float* pe = sm->PE + pr*65 + h0;
            n0 = fmaf(e0, v4.x + pe[0], n0);
            n1 = fmaf(e1, v4.y + pe[1], n1);
            n2 = fmaf(e2, v4.z + pe[2], n2);
            n3 = fmaf(e3, v4.w + pe[3], n3);
        }
        sm->Res[p*64 + h0 + 0] = n0 / d0;
        sm->Res[p*64 + h0 + 1] = n1 / d1;
        sm->Res[p*64 + h0 + 2] = n2 / d2;
        sm->Res[p*64 + h0 + 3] = n3 / d3;
    }
    __syncthreads();

    // ---- final: out = Res @ Wa + ba + features ----
    {
        int p  = tid >> 4;
        int h0 = (tid & 15) << 2;
        float a0 = 0.f, a1 = 0.f, a2 = 0.f, a3 = 0.f;
        #pragma unroll 8
        for (int i = 0; i < 64; i++) {
            float rr = sm->Res[p*64 + i];
            float4 w = *(const float4*)(sm->Wa + i*64 + h0);
            a0 = fmaf(rr, w.x, a0);
            a1 = fmaf(rr, w.y, a1);
            a2 = fmaf(rr, w.z, a2);
            a3 = fmaf(rr, w.w, a3);
        }
        int row = base + p;
        float4 f4 = *(const float4*)(features + (size_t)row*64 + h0);
        float4 o;
        o.x = a0 + sm->ba[h0 + 0] + f4.x;
        o.y = a1 + sm->ba[h0 + 1] + f4.y;
        o.z = a2 + sm->ba[h0 + 2] + f4.z;
        o.w = a3 + sm->ba[h0 + 3] + f4.w;
        *(float4*)(out + (size_t)row*64 + h0) = o;
    }
}

// ================= launch =================
extern "C" void kernel_launch(void* const* d_in, const int* in_sizes, int n_in,
                              void* d_out, int out_size) {
    const float* xyzp     = (const float*)d_in[0];
    const float* features = (const float*)d_in[1];
    const float* Wk  = (const float*)d_in[2];
    const float* bk  = (const float*)d_in[3];
    const float* Wq  = (const float*)d_in[4];
    const float* Wks = (const float*)d_in[5];
    const float* Wv  = (const float*)d_in[6];
    const float* Wp1 = (const float*)d_in[7];
    const float* bp1 = (const float*)d_in[8];
    const float* Wp2 = (const float*)d_in[9];
    const float* bp2 = (const float*)d_in[10];
    const float* Wt1 = (const float*)d_in[11];
    const float* bt1 = (const float*)d_in[12];
    const float* Wt2 = (const float*)d_in[13];
    const float* bt2 = (const float*)d_in[14];
    const float* Wa  = (const float*)d_in[15];
    const float* ba  = (const float*)d_in[16];
    float* out = (float*)d_out;

    cudaFuncSetAttribute(transform_kernel, cudaFuncAttributeMaxDynamicSharedMemorySize,
                         (int)sizeof(SmemT));
    cudaFuncSetAttribute(attn_kernel, cudaFuncAttributeMaxDynamicSharedMemorySize,
                         (int)sizeof(SmemA));

    fold_kernel<<<1, 256>>>(Wk, bk, Wq, Wks, Wv);
    transform_kernel<<<NP/16, 192, sizeof(SmemT)>>>(features, xyzp, Wp1);
    knn_kernel<<<128, 128>>>(xyzp);
    attn_kernel<<<NP/8, 128, sizeof(SmemA)>>>(features, bp1, Wp2, bp2,
                                              Wt1, bt1, Wt2, bt2, Wa, ba, out);
}

// round 6
// speedup vs baseline: 1.2354x; 1.2354x over previous
#include <cuda_runtime.h>

#define NB 2
#define NN 8192
#define NP (NB*NN)      // 16384 points total
#define KK 16
#define PAD 68          // row stride (floats) for attn stage buffers: conflict-free + 16B aligned

// ---------------- scratch (device globals; no allocation allowed) ----------------
__device__ float g_Wall[64*192];      // folded [i][c]: c 0-63 -> q, 64-127 -> k, 128-191 -> v
__device__ float g_call[192];         // folded biases
__device__ float g_X[NP*192];         // per-point q|k|v, row stride 192
__device__ float g_A[NP*64];          // per-point xyzp @ Wp1 (no bias)
__device__ int   g_idx[NP*KK];        // global neighbor row indices

__device__ __forceinline__ float finf() { return __int_as_float(0x7f800000); }

// ================= fold: Mq=Wk@Wq etc, cq=bk@Wq etc =================
__global__ void fold_kernel(const float* __restrict__ Wk, const float* __restrict__ bk,
                            const float* __restrict__ Wq, const float* __restrict__ Wks,
                            const float* __restrict__ Wv) {
    int tid = threadIdx.x;
    for (int e = tid; e < 4096; e += blockDim.x) {
        int i = e >> 6, h = e & 63;
        float sq = 0.f, sk = 0.f, sv = 0.f;
        #pragma unroll 4
        for (int k = 0; k < 64; k++) {
            float wk = Wk[i*64 + k];
            sq = fmaf(wk, Wq [k*64 + h], sq);
            sk = fmaf(wk, Wks[k*64 + h], sk);
            sv = fmaf(wk, Wv [k*64 + h], sv);
        }
        g_Wall[i*192 + h]        = sq;
        g_Wall[i*192 + 64 + h]   = sk;
        g_Wall[i*192 + 128 + h]  = sv;
    }
    if (tid < 192) {
        int sec = tid >> 6, h = tid & 63;
        const float* W = (sec == 0) ? Wq : ((sec == 1) ? Wks : Wv);
        float s = 0.f;
        #pragma unroll 4
        for (int k = 0; k < 64; k++) s = fmaf(bk[k], W[k*64 + h], s);
        g_call[tid] = s;
    }
}

// ================= transform: g_X = F @ Wall + call ; g_A = xyzp @ Wp1 =================
struct SmemT {
    float feat[16*65];     // padded rows
    float W[64*192];
    float c[192];
    float Wp1[4*64];
};

__global__ __launch_bounds__(192) void transform_kernel(
    const float* __restrict__ features, const float* __restrict__ xyzp,
    const float* __restrict__ Wp1) {
    extern __shared__ char smem_raw[];
    SmemT* sm = (SmemT*)smem_raw;
    int tid = threadIdx.x;            // 192 threads
    int base = blockIdx.x * 16;       // 16 rows per block

    for (int i4 = tid; i4 < 64*192/4; i4 += 192)
        ((float4*)sm->W)[i4] = ((const float4*)g_Wall)[i4];
    if (tid < 192) sm->c[tid] = g_call[tid];
    if (tid < 64)  ((float4*)sm->Wp1)[tid] = ((const float4*)Wp1)[tid];
    for (int i4 = tid; i4 < 16*64/4; i4 += 192) {
        int r = i4 >> 4, cc = i4 & 15;
        float4 v = ((const float4*)(features + (size_t)(base + r)*64))[cc];
        float* d = sm->feat + r*65 + cc*4;
        d[0] = v.x; d[1] = v.y; d[2] = v.z; d[3] = v.w;
    }
    __syncthreads();

    int rg = tid / 24;   // 0..7  -> rows rg*2 + {0,1}
    int cg = tid % 24;   // 0..23 -> cols cg*8 .. +7
    float acc[2][8];
    #pragma unroll
    for (int r = 0; r < 2; r++)
        #pragma unroll
        for (int c = 0; c < 8; c++) acc[r][c] = 0.f;

    #pragma unroll 4
    for (int i = 0; i < 64; i++) {
        float x0 = sm->feat[(rg*2    )*65 + i];
        float x1 = sm->feat[(rg*2 + 1)*65 + i];
        float4 w0 = *(const float4*)(sm->W + i*192 + cg*8);
        float4 w1 = *(const float4*)(sm->W + i*192 + cg*8 + 4);
        float wv[8] = {w0.x, w0.y, w0.z, w0.w, w1.x, w1.y, w1.z, w1.w};
        #pragma unroll
        for (int c = 0; c < 8; c++) {
            acc[0][c] = fmaf(x0, wv[c], acc[0][c]);
            acc[1][c] = fmaf(x1, wv[c], acc[1][c]);
        }
    }
    #pragma unroll
    for (int r = 0; r < 2; r++) {
        int row = base + rg*2 + r;
        float4 o0, o1;
        o0.x = acc[r][0] + sm->c[cg*8 + 0];
        o0.y = acc[r][1] + sm->c[cg*8 + 1];
        o0.z = acc[r][2] + sm->c[cg*8 + 2];
        o0.w = acc[r][3] + sm->c[cg*8 + 3];
        o1.x = acc[r][4] + sm->c[cg*8 + 4];
        o1.y = acc[r][5] + sm->c[cg*8 + 5];
        o1.z = acc[r][6] + sm->c[cg*8 + 6];
        o1.w = acc[r][7] + sm->c[cg*8 + 7];
        *(float4*)(g_X + (size_t)row*192 + cg*8)     = o0;
        *(float4*)(g_X + (size_t)row*192 + cg*8 + 4) = o1;
    }

    for (int o = tid; o < 16*64; o += 192) {
        int r = o >> 6, h = o & 63;
        const float* xp = xyzp + (size_t)(base + r)*4;
        float a = xp[0] * sm->Wp1[0*64 + h];
        a = fmaf(xp[1], sm->Wp1[1*64 + h], a);
        a = fmaf(xp[2], sm->Wp1[2*64 + h], a);
        a = fmaf(xp[3], sm->Wp1[3*64 + h], a);
        g_A[(size_t)(base + r)*64 + h] = a;
    }
}

// ================= knn =================
// 2 lanes per query. Pass 1: value-only top-16 via sorted-descending FMNMX bubble
// (tau = 16th smallest key per lane). Pass 2: collect (key,idx) with key <= tau as
// sortable u64. Merge: exact rank-count over the query's 2x20 region.
__global__ __launch_bounds__(128) void knn_kernel(const float* __restrict__ xyzp) {
    __shared__ float4 sT[2048];                 // 32 KB tile
    __shared__ unsigned long long sM[128*20];   // 20 KB merge region
    int tid  = threadIdx.x;                     // 128 threads: 64 queries x 2 lanes
    int b    = blockIdx.x >> 7;                 // 128 blocks per batch
    int qloc = tid >> 1, sub = tid & 1;
    int n    = ((blockIdx.x & 127) << 6) + qloc;
    int row  = b*NN + n;
    float4 me = __ldg(((const float4*)xyzp) + row);
    float xn = me.x, yn = me.y, zn = me.z;

    const float4* src = ((const float4*)xyzp) + (size_t)b*NN;
    int base = sub << 10;                       // lane's half of each 2048-tile

    float bk[16];
    #pragma unroll
    for (int s = 0; s < 16; s++) bk[s] = finf();

    // ---- pass 1: values only ----
    for (int t = 0; t < 4; t++) {
        #pragma unroll
        for (int k = 0; k < 16; k++) {
            int m = (k << 7) + tid;
            float4 p = __ldg(src + (t << 11) + m);
            p.w = fmaf(p.x, p.x, fmaf(p.y, p.y, p.z*p.z));
            sT[m] = p;
        }
        __syncthreads();
        #pragma unroll 4
        for (int i = 0; i < 1024; i++) {
            float4 c = sT[base + i];
            float key = fmaf(-2.f, fmaf(xn, c.x, fmaf(yn, c.y, zn*c.z)), c.w);
            if (key < bk[0]) {
                bk[0] = key;
                #pragma unroll
                for (int s = 0; s < 15; s++) {
                    float hi = fmaxf(bk[s], bk[s+1]);
                    float lo = fminf(bk[s], bk[s+1]);
                    bk[s] = hi; bk[s+1] = lo;
                }
            }
        }
        __syncthreads();
    }
    float tau = bk[0];

    unsigned long long* myreg = sM + (qloc*2 + sub)*20;
    #pragma unroll
    for (int e = 0; e < 20; e++) myreg[e] = ~0ULL;
    int cnt = 0;

    // ---- pass 2: recover indices ----
    for (int t = 0; t < 4; t++) {
        #pragma unroll
        for (int k = 0; k < 16; k++) {
            int m = (k << 7) + tid;
            float4 p = __ldg(src + (t << 11) + m);
            p.w = fmaf(p.x, p.x, fmaf(p.y, p.y, p.z*p.z));
            sT[m] = p;
        }
        __syncthreads();
        #pragma unroll 4
        for (int i = 0; i < 1024; i++) {
            float4 c = sT[base + i];
            float key = fmaf(-2.f, fmaf(xn, c.x, fmaf(yn, c.y, zn*c.z)), c.w);
            if (key <= tau && cnt < 20) {
                unsigned u = __float_as_uint(key);
                u ^= ((unsigned)((int)u >> 31)) | 0x80000000u;   // sortable
                myreg[cnt] = ((unsigned long long)u << 16) | (unsigned)((t << 11) + base + i);
                cnt++;
            }
        }
        __syncthreads();
    }

    // ---- merge: exact rank of my entries among the query's 40 ----
    unsigned long long mine[20];
    int rk[20];
    #pragma unroll
    for (int e = 0; e < 20; e++) { mine[e] = myreg[e]; rk[e] = 0; }
    const unsigned long long* qreg = sM + qloc*40;
    #pragma unroll 4
    for (int j = 0; j < 40; j++) {
        unsigned long long o = qreg[j];
        #pragma unroll
        for (int e = 0; e < 20; e++) rk[e] += (o < mine[e]);
    }
    #pragma unroll
    for (int e = 0; e < 20; e++)
        if (rk[e] < 16)
            g_idx[(size_t)row*16 + rk[e]] = b*NN + (int)(mine[e] & 0xFFFFULL);
}

// ================= fused attention: 4 points/block, 256 threads, 2 blocks/SM =================
struct SmemA {
    float Wp2[4096], Wt1[4096], Wt2[4096];
    float U[64*PAD];     // U -> then VPE (v + pos_enc)
    float Y[64*PAD];     // a_in -> relu(..) -> scores (in-place)
    float Res[4*64];
    int   Idx[64];
};

__device__ __forceinline__ void gemm2x8(const float* __restrict__ X, const float* __restrict__ W,
                                        int pg, int hg, float acc[2][8]) {
    #pragma unroll
    for (int r = 0; r < 2; r++)
        #pragma unroll
        for (int c = 0; c < 8; c++) acc[r][c] = 0.f;
    const float* xr = X + pg*2*PAD;
    const float* wb = W + hg*8;
    #pragma unroll 8
    for (int i = 0; i < 64; i++) {
        float x0 = xr[i];
        float x1 = xr[PAD + i];
        float4 w0 = *(const float4*)(wb + i*64);
        float4 w1 = *(const float4*)(wb + i*64 + 4);
        float wv[8] = {w0.x, w0.y, w0.z, w0.w, w1.x, w1.y, w1.z, w1.w};
        #pragma unroll
        for (int c = 0; c < 8; c++) {
            acc[0][c] = fmaf(x0, wv[c], acc[0][c]);
            acc[1][c] = fmaf(x1, wv[c], acc[1][c]);
        }
    }
}

__global__ __launch_bounds__(256, 2) void attn_kernel(
    const float* __restrict__ features,
    const float* __restrict__ bp1,
    const float* __restrict__ Wp2, const float* __restrict__ bp2,
    const float* __restrict__ Wt1, const float* __restrict__ bt1,
    const float* __restrict__ Wt2, const float* __restrict__ bt2,
    const float* __restrict__ Wa,  const float* __restrict__ ba,
    float* __restrict__ out) {
    extern __shared__ char smem_raw[];
    SmemA* sm = (SmemA*)smem_raw;
    int tid = threadIdx.x;       // 256
    int base = blockIdx.x * 4;   // 4 points / block

    #pragma unroll
    for (int i = tid; i < 1024; i += 256) {
        ((float4*)sm->Wp2)[i] = __ldg(((const float4*)Wp2) + i);
        ((float4*)sm->Wt1)[i] = __ldg(((const float4*)Wt1) + i);
        ((float4*)sm->Wt2)[i] = __ldg(((const float4*)Wt2) + i);
    }
    if (tid < 64) sm->Idx[tid] = g_idx[(size_t)base*16 + tid];
    __syncthreads();

    // ---- U[pair][i] = relu((A[n]+bp1) - A[j]) ----
    #pragma unroll
    for (int it = 0; it < 4; it++) {
        int flat = it*256 + tid;        // 0..1023
        int pair = flat >> 4, c4 = flat & 15;
        int p = pair >> 4;
        int g = sm->Idx[pair];
        float4 an = __ldg(((const float4*)(g_A + (size_t)(base + p)*64)) + c4);
        float4 bb = __ldg(((const float4*)bp1) + c4);
        float4 aj = __ldg(((const float4*)(g_A + (size_t)g*64)) + c4);
        float4 u;
        u.x = fmaxf(an.x + bb.x - aj.x, 0.f);
        u.y = fmaxf(an.y + bb.y - aj.y, 0.f);
        u.z = fmaxf(an.z + bb.z - aj.z, 0.f);
        u.w = fmaxf(an.w + bb.w - aj.w, 0.f);
        *(float4*)(sm->U + pair*PAD + c4*4) = u;
    }
    __syncthreads();

    int pg = tid >> 3;   // 0..31 -> rows pg*2 + {0,1}
    int hg = tid & 7;    // cols hg*8 .. +7
    float acc[2][8];

    // ---- GEMM1: pe = U @ Wp2 + bp2 ; Y = q - k + pe ; U := v + pe ----
    gemm2x8(sm->U, sm->Wp2, pg, hg, acc);
    __syncthreads();
    {
        int point = pg >> 3;
        const float4* qp = (const float4*)(g_X + (size_t)(base + point)*192 + hg*8);
        float4 q0 = __ldg(qp), q1 = __ldg(qp + 1);
        float qf[8] = {q0.x, q0.y, q0.z, q0.w, q1.x, q1.y, q1.z, q1.w};
        float4 b0 = __ldg(((const float4*)bp2) + hg*2);
        float4 b1 = __ldg(((const float4*)bp2) + hg*2 + 1);
        float bb[8] = {b0.x, b0.y, b0.z, b0.w, b1.x, b1.y, b1.z, b1.w};
        #pragma unroll
        for (int r = 0; r < 2; r++) {
            int pair = pg*2 + r;
            int g = sm->Idx[pair];
            const float4* kp = (const float4*)(g_X + (size_t)g*192 + 64 + hg*8);
            const float4* vp = (const float4*)(g_X + (size_t)g*192 + 128 + hg*8);
            float4 k0 = __ldg(kp), k1 = __ldg(kp + 1);
            float4 v0 = __ldg(vp), v1 = __ldg(vp + 1);
            float kf[8] = {k0.x, k0.y, k0.z, k0.w, k1.x, k1.y, k1.z, k1.w};
            float vf[8] = {v0.x, v0.y, v0.z, v0.w, v1.x, v1.y, v1.z, v1.w};
            float pe[8], yv[8], uv[8];
            #pragma unroll
            for (int c = 0; c < 8; c++) {
                pe[c] = acc[r][c] + bb[c];
                yv[c] = qf[c] - kf[c] + pe[c];
                uv[c] = vf[c] + pe[c];
            }
            float* yb = sm->Y + pair*PAD + hg*8;
            float* ub = sm->U + pair*PAD + hg*8;
            *(float4*)yb       = make_float4(yv[0], yv[1], yv[2], yv[3]);
            *(float4*)(yb + 4) = make_float4(yv[4], yv[5], yv[6], yv[7]);
            *(float4*)ub       = make_float4(uv[0], uv[1], uv[2], uv[3]);
            *(float4*)(ub + 4) = make_float4(uv[4], uv[5], uv[6], uv[7]);
        }
    }
    __syncthreads();

    // ---- GEMM2: Y := relu(Y @ Wt1 + bt1) (in-place) ----
    gemm2x8(sm->Y, sm->Wt1, pg, hg, acc);
    __syncthreads();
    {
        float4 b0 = __ldg(((const float4*)bt1) + hg*2);
        float4 b1 = __ldg(((const float4*)bt1) + hg*2 + 1);
        float bb[8] = {b0.x, b0.y, b0.z, b0.w, b1.x, b1.y, b1.z, b1.w};
        #pragma unroll
        for (int r = 0; r < 2; r++) {
            int pair = pg*2 + r;
            float* yb = sm->Y + pair*PAD + hg*8;
            float t[8];
            #pragma unroll
            for (int c = 0; c < 8; c++) t[c] = fmaxf(acc[r][c] + bb[c], 0.f);
            *(float4*)yb       = make_float4(t[0], t[1], t[2], t[3]);
            *(float4*)(yb + 4) = make_float4(t[4], t[5], t[6], t[7]);
        }
    }
    __syncthreads();

    // ---- GEMM3: Y := (Y @ Wt2 + bt2) / 8 (in-place) ----
    gemm2x8(sm->Y, sm->Wt2, pg, hg, acc);
    __syncthreads();
    {
        float4 b0 = __ldg(((const float4*)bt2) + hg*2);
        float4 b1 = __ldg(((const float4*)bt2) + hg*2 + 1);
        float bb[8] = {b0.x, b0.y, b0.z, b0.w, b1.x, b1.y, b1.z, b1.w};
        #pragma unroll
        for (int r = 0; r < 2; r++) {
            int pair = pg*2 + r;
            float* yb = sm->Y + pair*PAD + hg*8;
            float t[8];
            #pragma unroll
            for (int c = 0; c < 8; c++) t[c] = (acc[r][c] + bb[c]) * 0.125f;
            *(float4*)yb       = make_float4(t[0], t[1], t[2], t[3]);
            *(float4*)(yb + 4) = make_float4(t[4], t[5], t[6], t[7]);
        }
    }
    __syncthreads();

    // ---- softmax over j + weighted sum with VPE ----
    {
        int p = tid >> 6, h = tid & 63;
        float m = -finf();
        #pragma unroll
        for (int j = 0; j < 16; j++)
            m = fmaxf(m, sm->Y[(p*16 + j)*PAD + h]);
        float num = 0.f, den = 0.f;
        #pragma unroll
        for (int j = 0; j < 16; j++) {
            float e = __expf(sm->Y[(p*16 + j)*PAD + h] - m);
            den += e;
            num = fmaf(e, sm->U[(p*16 + j)*PAD + h], num);
        }
        sm->Res[p*64 + h] = num / den;
    }
    __syncthreads();

    // ---- final: out = Res @ Wa + ba + features ----
    {
        int p = tid >> 6, h = tid & 63;
        float a = 0.f;
        const float* wa = Wa + h;
        #pragma unroll 8
        for (int i = 0; i < 64; i++)
            a = fmaf(sm->Res[p*64 + i], __ldg(wa + i*64), a);
        int row = base + p;
        out[(size_t)row*64 + h] = a + __ldg(ba + h) + __ldg(features + (size_t)row*64 + h);
    }
}

// ================= launch =================
extern "C" void kernel_launch(void* const* d_in, const int* in_sizes, int n_in,
                              void* d_out, int out_size) {
    const float* xyzp     = (const float*)d_in[0];
    const float* features = (const float*)d_in[1];
    const float* Wk  = (const float*)d_in[2];
    const float* bk  = (const float*)d_in[3];
    const float* Wq  = (const float*)d_in[4];
    const float* Wks = (const float*)d_in[5];
    const float* Wv  = (const float*)d_in[6];
    const float* Wp1 = (const float*)d_in[7];
    const float* bp1 = (const float*)d_in[8];
    const float* Wp2 = (const float*)d_in[9];
    const float* bp2 = (const float*)d_in[10];
    const float* Wt1 = (const float*)d_in[11];
    const float* bt1 = (const float*)d_in[12];
    const float* Wt2 = (const float*)d_in[13];
    const float* bt2 = (const float*)d_in[14];
    const float* Wa  = (const float*)d_in[15];
    const float* ba  = (const float*)d_in[16];
    float* out = (float*)d_out;

    cudaFuncSetAttribute(transform_kernel, cudaFuncAttributeMaxDynamicSharedMemorySize,
                         (int)sizeof(SmemT));
    cudaFuncSetAttribute(attn_kernel, cudaFuncAttributeMaxDynamicSharedMemorySize,
                         (int)sizeof(SmemA));

    fold_kernel<<<1, 512>>>(Wk, bk, Wq, Wks, Wv);
    transform_kernel<<<NP/16, 192, sizeof(SmemT)>>>(features, xyzp, Wp1);
    knn_kernel<<<256, 128>>>(xyzp);
    attn_kernel<<<NP/4, 256, sizeof(SmemA)>>>(features, bp1, Wp2, bp2,
                                              Wt1, bt1, Wt2, bt2, Wa, ba, out);
}

// round 7
// speedup vs baseline: 1.4212x; 1.1504x over previous
#include <cuda_runtime.h>

#define NB 2
#define NN 8192
#define NP (NB*NN)      // 16384 points total
#define KK 16
#define PAD 68          // row stride (floats) for attn stage buffers
#define PTS 6           // points per attn block
#define PRS (PTS*16)    // 96 pairs per attn block

// ---------------- scratch (device globals; no allocation allowed) ----------------
__device__ float g_Wall[64*192];      // folded [i][c]: c 0-63 -> q, 64-127 -> k, 128-191 -> v
__device__ float g_call[192];         // folded biases
__device__ float g_X[NP*192];         // per-point q|k|v, row stride 192
__device__ float g_A[NP*64];          // per-point xyzp @ Wp1 (no bias)
__device__ int   g_idx[NP*KK];        // global neighbor row indices

__device__ __forceinline__ float finf() { return __int_as_float(0x7f800000); }

// ================= fold: Mq=Wk@Wq etc, cq=bk@Wq etc =================
__global__ void fold_kernel(const float* __restrict__ Wk, const float* __restrict__ bk,
                            const float* __restrict__ Wq, const float* __restrict__ Wks,
                            const float* __restrict__ Wv) {
    int tid = threadIdx.x;
    for (int e = tid; e < 4096; e += blockDim.x) {
        int i = e >> 6, h = e & 63;
        float sq = 0.f, sk = 0.f, sv = 0.f;
        #pragma unroll 4
        for (int k = 0; k < 64; k++) {
            float wk = Wk[i*64 + k];
            sq = fmaf(wk, Wq [k*64 + h], sq);
            sk = fmaf(wk, Wks[k*64 + h], sk);
            sv = fmaf(wk, Wv [k*64 + h], sv);
        }
        g_Wall[i*192 + h]        = sq;
        g_Wall[i*192 + 64 + h]   = sk;
        g_Wall[i*192 + 128 + h]  = sv;
    }
    if (tid < 192) {
        int sec = tid >> 6, h = tid & 63;
        const float* W = (sec == 0) ? Wq : ((sec == 1) ? Wks : Wv);
        float s = 0.f;
        #pragma unroll 4
        for (int k = 0; k < 64; k++) s = fmaf(bk[k], W[k*64 + h], s);
        g_call[tid] = s;
    }
}

// ================= transform: g_X = F @ Wall + call ; g_A = xyzp @ Wp1 =================
struct SmemT {
    float feat[16*65];
    float W[64*192];
    float c[192];
    float Wp1[4*64];
};

__global__ __launch_bounds__(192) void transform_kernel(
    const float* __restrict__ features, const float* __restrict__ xyzp,
    const float* __restrict__ Wp1) {
    extern __shared__ char smem_raw[];
    SmemT* sm = (SmemT*)smem_raw;
    int tid = threadIdx.x;            // 192 threads
    int base = blockIdx.x * 16;       // 16 rows per block

    for (int i4 = tid; i4 < 64*192/4; i4 += 192)
        ((float4*)sm->W)[i4] = ((const float4*)g_Wall)[i4];
    if (tid < 192) sm->c[tid] = g_call[tid];
    if (tid < 64)  ((float4*)sm->Wp1)[tid] = ((const float4*)Wp1)[tid];
    for (int i4 = tid; i4 < 16*64/4; i4 += 192) {
        int r = i4 >> 4, cc = i4 & 15;
        float4 v = ((const float4*)(features + (size_t)(base + r)*64))[cc];
        float* d = sm->feat + r*65 + cc*4;
        d[0] = v.x; d[1] = v.y; d[2] = v.z; d[3] = v.w;
    }
    __syncthreads();

    int rg = tid / 24;
    int cg = tid % 24;
    float acc[2][8];
    #pragma unroll
    for (int r = 0; r < 2; r++)
        #pragma unroll
        for (int c = 0; c < 8; c++) acc[r][c] = 0.f;

    #pragma unroll 4
    for (int i = 0; i < 64; i++) {
        float x0 = sm->feat[(rg*2    )*65 + i];
        float x1 = sm->feat[(rg*2 + 1)*65 + i];
        float4 w0 = *(const float4*)(sm->W + i*192 + cg*8);
        float4 w1 = *(const float4*)(sm->W + i*192 + cg*8 + 4);
        float wv[8] = {w0.x, w0.y, w0.z, w0.w, w1.x, w1.y, w1.z, w1.w};
        #pragma unroll
        for (int c = 0; c < 8; c++) {
            acc[0][c] = fmaf(x0, wv[c], acc[0][c]);
            acc[1][c] = fmaf(x1, wv[c], acc[1][c]);
        }
    }
    #pragma unroll
    for (int r = 0; r < 2; r++) {
        int row = base + rg*2 + r;
        float4 o0, o1;
        o0.x = acc[r][0] + sm->c[cg*8 + 0];
        o0.y = acc[r][1] + sm->c[cg*8 + 1];
        o0.z = acc[r][2] + sm->c[cg*8 + 2];
        o0.w = acc[r][3] + sm->c[cg*8 + 3];
        o1.x = acc[r][4] + sm->c[cg*8 + 4];
        o1.y = acc[r][5] + sm->c[cg*8 + 5];
        o1.z = acc[r][6] + sm->c[cg*8 + 6];
        o1.w = acc[r][7] + sm->c[cg*8 + 7];
        *(float4*)(g_X + (size_t)row*192 + cg*8)     = o0;
        *(float4*)(g_X + (size_t)row*192 + cg*8 + 4) = o1;
    }

    for (int o = tid; o < 16*64; o += 192) {
        int r = o >> 6, h = o & 63;
        const float* xp = xyzp + (size_t)(base + r)*4;
        float a = xp[0] * sm->Wp1[0*64 + h];
        a = fmaf(xp[1], sm->Wp1[1*64 + h], a);
        a = fmaf(xp[2], sm->Wp1[2*64 + h], a);
        a = fmaf(xp[3], sm->Wp1[3*64 + h], a);
        g_A[(size_t)(base + r)*64 + h] = a;
    }
}

// ================= knn: single pass, 4 lanes/query, (key,idx) sorted insert =================
__global__ __launch_bounds__(128) void knn_kernel(const float* __restrict__ xyzp) {
    __shared__ float4 sT[2048];                      // 32 KB candidate tile
    __shared__ unsigned long long sM[128*16];        // 16 KB merge region
    int tid  = threadIdx.x;                          // 128: 32 queries x 4 lanes
    int b    = blockIdx.x >> 8;                      // 256 blocks per batch
    int qloc = tid >> 2, sub = tid & 3;
    int n    = ((blockIdx.x & 255) << 5) + qloc;
    int row  = b*NN + n;
    float4 me = __ldg(((const float4*)xyzp) + row);
    float xn = me.x, yn = me.y, zn = me.z;
    const float4* src = ((const float4*)xyzp) + (size_t)b*NN;
    int lb = sub << 9;                               // lane's 512-range in each tile

    float bk[16];
    int   bi[16];
    #pragma unroll
    for (int s = 0; s < 16; s++) { bk[s] = finf(); bi[s] = 0; }

    for (int t = 0; t < 4; t++) {
        #pragma unroll
        for (int k = 0; k < 16; k++) {
            int m = (k << 7) + tid;
            float4 p = __ldg(src + (t << 11) + m);
            p.w = fmaf(p.x, p.x, fmaf(p.y, p.y, p.z*p.z));
            sT[m] = p;
        }
        __syncthreads();
        #pragma unroll 4
        for (int i = 0; i < 512; i++) {
            float4 c = sT[lb + i];
            float key = fmaf(-2.f, fmaf(xn, c.x, fmaf(yn, c.y, zn*c.z)), c.w);
            if (key < bk[0]) {
                bk[0] = key;
                bi[0] = (t << 11) + lb + i;
                #pragma unroll
                for (int s = 0; s < 15; s++) {
                    bool csw = bk[s] < bk[s+1];
                    float hi = fmaxf(bk[s], bk[s+1]);
                    float lo = fminf(bk[s], bk[s+1]);
                    int ih = csw ? bi[s+1] : bi[s];
                    int il = csw ? bi[s]   : bi[s+1];
                    bk[s] = hi; bk[s+1] = lo;
                    bi[s] = ih; bi[s+1] = il;
                }
            }
        }
        __syncthreads();
    }

    // dump as sortable u64 = (sortable_key << 13) | local_idx
    unsigned long long* my = sM + tid*16;
    #pragma unroll
    for (int s = 0; s < 16; s++) {
        unsigned u = __float_as_uint(bk[s]);
        u ^= ((unsigned)((int)u >> 31)) | 0x80000000u;
        my[s] = ((unsigned long long)u << 13) | (unsigned)bi[s];
    }
    __syncthreads();

    // exact rank of my 16 among the query's 64 (all distinct via idx bits)
    unsigned long long mine[16];
    int rk[16];
    #pragma unroll
    for (int e = 0; e < 16; e++) { mine[e] = my[e]; rk[e] = 0; }
    const unsigned long long* qreg = sM + qloc*64;
    #pragma unroll 4
    for (int j = 0; j < 64; j++) {
        unsigned long long o = qreg[j];
        #pragma unroll
        for (int e = 0; e < 16; e++) rk[e] += (o < mine[e]);
    }
    #pragma unroll
    for (int e = 0; e < 16; e++)
        if (rk[e] < 16)
            g_idx[(size_t)row*16 + rk[e]] = b*NN + (int)(mine[e] & 0x1FFFULL);
}

// ================= fused attention: 6 points/block, 192 threads, 2 blocks/SM =================
struct SmemA {
    float Wp2[4096], Wt1[4096], Wt2[4096];
    float U[PRS*PAD];     // relu(pos) -> then VPE (v + pos_enc)
    float Y[PRS*PAD];     // a_in -> relu -> scores (in-place)
    float Res[PTS*64];
    int   Idx[PRS];
};

// 4x8 tile; thread owns rows pg + 24*r (strided -> conflict-free x loads)
__device__ __forceinline__ void gemm4x8(const float* __restrict__ X, const float* __restrict__ W,
                                        int pg, int hg, float acc[4][8]) {
    #pragma unroll
    for (int r = 0; r < 4; r++)
        #pragma unroll
        for (int c = 0; c < 8; c++) acc[r][c] = 0.f;
    const float* wb = W + hg*8;
    #pragma unroll 2
    for (int i4 = 0; i4 < 16; i4++) {
        float xa[4][4];
        #pragma unroll
        for (int r = 0; r < 4; r++)
            *(float4*)xa[r] = *(const float4*)(X + (pg + 24*r)*PAD + i4*4);
        #pragma unroll
        for (int ii = 0; ii < 4; ii++) {
            int i = i4*4 + ii;
            float4 w0 = *(const float4*)(wb + i*64);
            float4 w1 = *(const float4*)(wb + i*64 + 4);
            float wv[8] = {w0.x, w0.y, w0.z, w0.w, w1.x, w1.y, w1.z, w1.w};
            #pragma unroll
            for (int r = 0; r < 4; r++)
                #pragma unroll
                for (int c = 0; c < 8; c++)
                    acc[r][c] = fmaf(xa[r][ii], wv[c], acc[r][c]);
        }
    }
}

__global__ __launch_bounds__(192, 2) void attn_kernel(
    const float* __restrict__ features,
    const float* __restrict__ bp1,
    const float* __restrict__ Wp2, const float* __restrict__ bp2,
    const float* __restrict__ Wt1, const float* __restrict__ bt1,
    const float* __restrict__ Wt2, const float* __restrict__ bt2,
    const float* __restrict__ Wa,  const float* __restrict__ ba,
    float* __restrict__ out) {
    extern __shared__ char smem_raw[];
    SmemA* sm = (SmemA*)smem_raw;
    int tid = threadIdx.x;        // 192
    int base = blockIdx.x * PTS;  // 6 points / block (last block partial)

    for (int i = tid; i < 1024; i += 192) {
        ((float4*)sm->Wp2)[i] = __ldg(((const float4*)Wp2) + i);
        ((float4*)sm->Wt1)[i] = __ldg(((const float4*)Wt1) + i);
        ((float4*)sm->Wt2)[i] = __ldg(((const float4*)Wt2) + i);
    }
    if (tid < PRS) {
        int prow = min(base + (tid >> 4), NP-1);
        sm->Idx[tid] = g_idx[(size_t)prow*16 + (tid & 15)];
    }
    __syncthreads();

    // ---- U[pair][i] = relu((A[n]+bp1) - A[j]) ----
    #pragma unroll
    for (int it = 0; it < 8; it++) {
        int flat = it*192 + tid;          // 0..1535
        int pair = flat >> 4, c4 = flat & 15;
        int prow = min(base + (pair >> 4), NP-1);
        int g = sm->Idx[pair];
        float4 an = __ldg(((const float4*)(g_A + (size_t)prow*64)) + c4);
        float4 bb = __ldg(((const float4*)bp1) + c4);
        float4 aj = __ldg(((const float4*)(g_A + (size_t)g*64)) + c4);
        float4 u;
        u.x = fmaxf(an.x + bb.x - aj.x, 0.f);
        u.y = fmaxf(an.y + bb.y - aj.y, 0.f);
        u.z = fmaxf(an.z + bb.z - aj.z, 0.f);
        u.w = fmaxf(an.w + bb.w - aj.w, 0.f);
        *(float4*)(sm->U + pair*PAD + c4*4) = u;
    }
    __syncthreads();

    int pg = tid >> 3;   // 0..23, rows pg + 24*r
    int hg = tid & 7;    // cols hg*8 .. +7
    float acc[4][8];

    // ---- GEMM1: pe = U @ Wp2 + bp2 ; Y = q - k + pe ; U := v + pe ----
    gemm4x8(sm->U, sm->Wp2, pg, hg, acc);
    __syncthreads();
    {
        float4 b0 = __ldg(((const float4*)bp2) + hg*2);
        float4 b1 = __ldg(((const float4*)bp2) + hg*2 + 1);
        float bb[8] = {b0.x, b0.y, b0.z, b0.w, b1.x, b1.y, b1.z, b1.w};
        #pragma unroll
        for (int r = 0; r < 4; r++) {
            int pair = pg + 24*r;
            int prow = min(base + (pair >> 4), NP-1);
            const float4* qp = (const float4*)(g_X + (size_t)prow*192) + hg*2;
            float4 q0 = __ldg(qp), q1 = __ldg(qp + 1);
            float qf[8] = {q0.x, q0.y, q0.z, q0.w, q1.x, q1.y, q1.z, q1.w};
            int g = sm->Idx[pair];
            const float4* kp = (const float4*)(g_X + (size_t)g*192 + 64) + hg*2;
            const float4* vp = (const float4*)(g_X + (size_t)g*192 + 128) + hg*2;
            float4 k0 = __ldg(kp), k1 = __ldg(kp + 1);
            float4 v0 = __ldg(vp), v1 = __ldg(vp + 1);
            float kf[8] = {k0.x, k0.y, k0.z, k0.w, k1.x, k1.y, k1.z, k1.w};
            float vf[8] = {v0.x, v0.y, v0.z, v0.w, v1.x, v1.y, v1.z, v1.w};
            float yv[8], uv[8];
            #pragma unroll
            for (int c = 0; c < 8; c++) {
                float pe = acc[r][c] + bb[c];
                yv[c] = qf[c] - kf[c] + pe;
                uv[c] = vf[c] + pe;
            }
            float* yb = sm->Y + pair*PAD + hg*8;
            float* ub = sm->U + pair*PAD + hg*8;
            *(float4*)yb       = make_float4(yv[0], yv[1], yv[2], yv[3]);
            *(float4*)(yb + 4) = make_float4(yv[4], yv[5], yv[6], yv[7]);
            *(float4*)ub       = make_float4(uv[0], uv[1], uv[2], uv[3]);
            *(float4*)(ub + 4) = make_float4(uv[4], uv[5], uv[6], uv[7]);
        }
    }
    __syncthreads();

    // ---- GEMM2: Y := relu(Y @ Wt1 + bt1) ----
    gemm4x8(sm->Y, sm->Wt1, pg, hg, acc);
    __syncthreads();
    {
        float4 b0 = __ldg(((const float4*)bt1) + hg*2);
        float4 b1 = __ldg(((const float4*)bt1) + hg*2 + 1);
        float bb[8] = {b0.x, b0.y, b0.z, b0.w, b1.x, b1.y, b1.z, b1.w};
        #pragma unroll
        for (int r = 0; r < 4; r++) {
            float* yb = sm->Y + (pg + 24*r)*PAD + hg*8;
            float t[8];
            #pragma unroll
            for (int c = 0; c < 8; c++) t[c] = fmaxf(acc[r][c] + bb[c], 0.f);
            *(float4*)yb       = make_float4(t[0], t[1], t[2], t[3]);
            *(float4*)(yb + 4) = make_float4(t[4], t[5], t[6], t[7]);
        }
    }
    __syncthreads();

    // ---- GEMM3: Y := (Y @ Wt2 + bt2) / 8 ----
    gemm4x8(sm->Y, sm->Wt2, pg, hg, acc);
    __syncthreads();
    {
        float4 b0 = __ldg(((const float4*)bt2) + hg*2);
        float4 b1 = __ldg(((const float4*)bt2) + hg*2 + 1);
        float bb[8] = {b0.x, b0.y, b0.z, b0.w, b1.x, b1.y, b1.z, b1.w};
        #pragma unroll
        for (int r = 0; r < 4; r++) {
            float* yb = sm->Y + (pg + 24*r)*PAD + hg*8;
            float t[8];
            #pragma unroll
            for (int c = 0; c < 8; c++) t[c] = (acc[r][c] + bb[c]) * 0.125f;
            *(float4*)yb       = make_float4(t[0], t[1], t[2], t[3]);
            *(float4*)(yb + 4) = make_float4(t[4], t[5], t[6], t[7]);
        }
    }
    __syncthreads();

    // ---- softmax over j + weighted sum with VPE ----
    #pragma unroll
    for (int e = tid; e < PTS*64; e += 192) {
        int p = e >> 6, h = e & 63;
        float m = -finf();
        #pragma unroll
        for (int j = 0; j < 16; j++)
            m = fmaxf(m, sm->Y[(p*16 + j)*PAD + h]);
        float num = 0.f, den = 0.f;
        #pragma unroll
        for (int j = 0; j < 16; j++) {
            float ex = __expf(sm->Y[(p*16 + j)*PAD + h] - m);
            den += ex;
            num = fmaf(ex, sm->U[(p*16 + j)*PAD + h], num);
        }
        sm->Res[p*64 + h] = num / den;
    }
    __syncthreads();

    // ---- final: out = Res @ Wa + ba + features ----
    #pragma unroll
    for (int e = tid; e < PTS*64; e += 192) {
        int p = e >> 6, h = e & 63;
        int row = base + p;
        if (row < NP) {
            float a = 0.f;
            const float* wa = Wa + h;
            #pragma unroll 8
            for (int i = 0; i < 64; i++)
                a = fmaf(sm->Res[p*64 + i], __ldg(wa + i*64), a);
            out[(size_t)row*64 + h] = a + __ldg(ba + h) + __ldg(features + (size_t)row*64 + h);
        }
    }
}

// ================= launch =================
extern "C" void kernel_launch(void* const* d_in, const int* in_sizes, int n_in,
                              void* d_out, int out_size) {
    const float* xyzp     = (const float*)d_in[0];
    const float* features = (const float*)d_in[1];
    const float* Wk  = (const float*)d_in[2];
    const float* bk  = (const float*)d_in[3];
    const float* Wq  = (const float*)d_in[4];
    const float* Wks = (const float*)d_in[5];
    const float* Wv  = (const float*)d_in[6];
    const float* Wp1 = (const float*)d_in[7];
    const float* bp1 = (const float*)d_in[8];
    const float* Wp2 = (const float*)d_in[9];
    const float* bp2 = (const float*)d_in[10];
    const float* Wt1 = (const float*)d_in[11];
    const float* bt1 = (const float*)d_in[12];
    const float* Wt2 = (const float*)d_in[13];
    const float* bt2 = (const float*)d_in[14];
    const float* Wa  = (const float*)d_in[15];
    const float* ba  = (const float*)d_in[16];
    float* out = (float*)d_out;

    cudaFuncSetAttribute(transform_kernel, cudaFuncAttributeMaxDynamicSharedMemorySize,
                         (int)sizeof(SmemT));
    cudaFuncSetAttribute(attn_kernel, cudaFuncAttributeMaxDynamicSharedMemorySize,
                         (int)sizeof(SmemA));

    fold_kernel<<<1, 512>>>(Wk, bk, Wq, Wks, Wv);
    transform_kernel<<<NP/16, 192, sizeof(SmemT)>>>(features, xyzp, Wp1);
    knn_kernel<<<512, 128>>>(xyzp);
    int attn_grid = (NP + PTS - 1) / PTS;
    attn_kernel<<<attn_grid, 192, sizeof(SmemA)>>>(features, bp1, Wp2, bp2,
                                                   Wt1, bt1, Wt2, bt2, Wa, ba, out);
}

// round 8
// speedup vs baseline: 1.6617x; 1.1692x over previous
#include <cuda_runtime.h>

#define NB 2
#define NN 8192
#define NP (NB*NN)      // 16384 points total
#define KK 16
#define PAD 68          // row stride (floats) for attn stage buffers
#define PTS 6           // points per attn block
#define PRS (PTS*16)    // 96 pairs per attn block
#define CAPA 24         // knn append-buffer capacity per lane

// ---------------- scratch (device globals; no allocation allowed) ----------------
__device__ float g_Wall[64*192];      // folded [i][c]: c 0-63 -> q, 64-127 -> k, 128-191 -> v
__device__ float g_call[192];         // folded biases
__device__ float g_X[NP*192];         // per-point q|k|v, row stride 192
__device__ float g_A[NP*64];          // per-point xyzp @ Wp1 (no bias)
__device__ int   g_idx[NP*KK];        // global neighbor row indices
__device__ float4 g_pts[NP];          // (x, y, z, |xyz|^2)

__device__ __forceinline__ float finf() { return __int_as_float(0x7f800000); }

// ================= fold: Mq=Wk@Wq etc, cq=bk@Wq etc =================
__global__ void fold_kernel(const float* __restrict__ Wk, const float* __restrict__ bk,
                            const float* __restrict__ Wq, const float* __restrict__ Wks,
                            const float* __restrict__ Wv) {
    int e = blockIdx.x * 256 + threadIdx.x;   // grid 16 x 256 = 4096
    int i = e >> 6, h = e & 63;
    float sq = 0.f, sk = 0.f, sv = 0.f;
    #pragma unroll 4
    for (int k = 0; k < 64; k++) {
        float wk = Wk[i*64 + k];
        sq = fmaf(wk, Wq [k*64 + h], sq);
        sk = fmaf(wk, Wks[k*64 + h], sk);
        sv = fmaf(wk, Wv [k*64 + h], sv);
    }
    g_Wall[i*192 + h]        = sq;
    g_Wall[i*192 + 64 + h]   = sk;
    g_Wall[i*192 + 128 + h]  = sv;
    if (blockIdx.x == 0 && threadIdx.x < 192) {
        int sec = threadIdx.x >> 6, hh = threadIdx.x & 63;
        const float* W = (sec == 0) ? Wq : ((sec == 1) ? Wks : Wv);
        float s = 0.f;
        #pragma unroll 4
        for (int k = 0; k < 64; k++) s = fmaf(bk[k], W[k*64 + hh], s);
        g_call[threadIdx.x] = s;
    }
}

// ================= transform: g_X = F @ Wall + call ; g_A = xyzp @ Wp1 ; g_pts =================
struct SmemT {
    float feat[16*65];
    float W[64*192];
    float c[192];
    float Wp1[4*64];
};

__global__ __launch_bounds__(192) void transform_kernel(
    const float* __restrict__ features, const float* __restrict__ xyzp,
    const float* __restrict__ Wp1) {
    extern __shared__ char smem_raw[];
    SmemT* sm = (SmemT*)smem_raw;
    int tid = threadIdx.x;            // 192 threads
    int base = blockIdx.x * 16;       // 16 rows per block

    for (int i4 = tid; i4 < 64*192/4; i4 += 192)
        ((float4*)sm->W)[i4] = ((const float4*)g_Wall)[i4];
    if (tid < 192) sm->c[tid] = g_call[tid];
    if (tid < 64)  ((float4*)sm->Wp1)[tid] = ((const float4*)Wp1)[tid];
    for (int i4 = tid; i4 < 16*64/4; i4 += 192) {
        int r = i4 >> 4, cc = i4 & 15;
        float4 v = ((const float4*)(features + (size_t)(base + r)*64))[cc];
        float* d = sm->feat + r*65 + cc*4;
        d[0] = v.x; d[1] = v.y; d[2] = v.z; d[3] = v.w;
    }
    if (tid < 16) {
        float4 p = ((const float4*)xyzp)[base + tid];
        float s = fmaf(p.x, p.x, fmaf(p.y, p.y, p.z*p.z));
        g_pts[base + tid] = make_float4(p.x, p.y, p.z, s);
    }
    __syncthreads();

    int rg = tid / 24;
    int cg = tid % 24;
    float acc[2][8];
    #pragma unroll
    for (int r = 0; r < 2; r++)
        #pragma unroll
        for (int c = 0; c < 8; c++) acc[r][c] = 0.f;

    #pragma unroll 4
    for (int i = 0; i < 64; i++) {
        float x0 = sm->feat[(rg*2    )*65 + i];
        float x1 = sm->feat[(rg*2 + 1)*65 + i];
        float4 w0 = *(const float4*)(sm->W + i*192 + cg*8);
        float4 w1 = *(const float4*)(sm->W + i*192 + cg*8 + 4);
        float wv[8] = {w0.x, w0.y, w0.z, w0.w, w1.x, w1.y, w1.z, w1.w};
        #pragma unroll
        for (int c = 0; c < 8; c++) {
            acc[0][c] = fmaf(x0, wv[c], acc[0][c]);
            acc[1][c] = fmaf(x1, wv[c], acc[1][c]);
        }
    }
    #pragma unroll
    for (int r = 0; r < 2; r++) {
        int row = base + rg*2 + r;
        float4 o0, o1;
        o0.x = acc[r][0] + sm->c[cg*8 + 0];
        o0.y = acc[r][1] + sm->c[cg*8 + 1];
        o0.z = acc[r][2] + sm->c[cg*8 + 2];
        o0.w = acc[r][3] + sm->c[cg*8 + 3];
        o1.x = acc[r][4] + sm->c[cg*8 + 4];
        o1.y = acc[r][5] + sm->c[cg*8 + 5];
        o1.z = acc[r][6] + sm->c[cg*8 + 6];
        o1.w = acc[r][7] + sm->c[cg*8 + 7];
        *(float4*)(g_X + (size_t)row*192 + cg*8)     = o0;
        *(float4*)(g_X + (size_t)row*192 + cg*8 + 4) = o1;
    }

    for (int o = tid; o < 16*64; o += 192) {
        int r = o >> 6, h = o & 63;
        const float* xp = xyzp + (size_t)(base + r)*4;
        float a = xp[0] * sm->Wp1[0*64 + h];
        a = fmaf(xp[1], sm->Wp1[1*64 + h], a);
        a = fmaf(xp[2], sm->Wp1[2*64 + h], a);
        a = fmaf(xp[3], sm->Wp1[3*64 + h], a);
        g_A[(size_t)(base + r)*64 + h] = a;
    }
}

// ================= knn: branchless append-buffer + deferred warp-uniform compaction =======
// 4 lanes/query, each scans a 2048 slice. Inner loop: ALWAYS store {key,idx} to slot cnt,
// cnt += (key<=tau). Every 8 candidates a uniform ballot triggers compaction: merge the
// <=24 buffered entries into the persistent register sorted-16 (FMNMX bubble), reset cnt,
// refresh tau = min over the query's 4 lanes of bk[0] (conservative bound, never rejects a
// true global top-16). Final merge: exact rank-count on sortable u64s.
__device__ __forceinline__ void knn_merge16(float bk[16], int bi[16], float f, int ix) {
    bool t = f < bk[0];
    bk[0] = t ? f : bk[0];
    bi[0] = t ? ix : bi[0];
    #pragma unroll
    for (int s = 0; s < 15; s++) {
        bool csw = bk[s] < bk[s+1];
        float hi = fmaxf(bk[s], bk[s+1]);
        float lo = fminf(bk[s], bk[s+1]);
        int ih = csw ? bi[s+1] : bi[s];
        int il = csw ? bi[s]   : bi[s+1];
        bk[s] = hi; bk[s+1] = lo;
        bi[s] = ih; bi[s+1] = il;
    }
}

__global__ __launch_bounds__(128) void knn_kernel() {
    __shared__ unsigned long long sB[CAPA*128];   // per-lane buffer, entry e at [e*128+tid]
    int tid  = threadIdx.x;                       // 128: 32 queries x 4 lanes
    int b    = blockIdx.x >> 8;                   // 256 blocks per batch
    int qloc = tid >> 2, sub = tid & 3;
    int n    = ((blockIdx.x & 255) << 5) + qloc;
    int row  = b*NN + n;
    float4 me = __ldg(&g_pts[row]);
    float xn = me.x, yn = me.y, zn = me.z;
    const float4* src = g_pts + (size_t)b*NN + (sub << 11);  // lane's 2048 range
    int jg0 = sub << 11;

    float bk[16];
    int   bi[16];
    #pragma unroll
    for (int s = 0; s < 16; s++) { bk[s] = finf(); bi[s] = 0; }
    float tau = finf();
    int cnt = 0;

    for (int ch = 0; ch < 256; ch++) {
        #pragma unroll
        for (int u = 0; u < 8; u++) {
            int j = (ch << 3) + u;
            float4 c = __ldg(src + j);
            float f = fmaf(-2.f, fmaf(xn, c.x, fmaf(yn, c.y, zn*c.z)), c.w);
            ((float2*)sB)[cnt*128 + tid] = make_float2(f, __int_as_float(jg0 + j));
            cnt += (f <= tau) ? 1 : 0;
        }
        if (__ballot_sync(0xffffffffu, cnt > 16)) {
            for (int e = 0; e < cnt; e++) {
                float2 en = ((float2*)sB)[e*128 + tid];
                knn_merge16(bk, bi, en.x, __float_as_int(en.y));
            }
            cnt = 0;
            float t0 = fminf(bk[0], __shfl_xor_sync(0xffffffffu, bk[0], 1));
            tau = fminf(t0, __shfl_xor_sync(0xffffffffu, t0, 2));
        }
    }
    // final compaction (uniform)
    for (int e = 0; e < cnt; e++) {
        float2 en = ((float2*)sB)[e*128 + tid];
        knn_merge16(bk, bi, en.x, __float_as_int(en.y));
    }

    // pack final 16 as sortable u64 and publish for merge
    unsigned long long mine[16];
    #pragma unroll
    for (int s = 0; s < 16; s++) {
        unsigned u = __float_as_uint(bk[s]);
        u ^= ((unsigned)((int)u >> 31)) | 0x80000000u;
        mine[s] = ((unsigned long long)u << 13) | (unsigned)bi[s];
        sB[s*128 + tid] = mine[s];
    }
    __syncwarp();

    // exact rank of my 16 among the query's 64 (distinct: disjoint idx ranges)
    int rk[16];
    #pragma unroll
    for (int s = 0; s < 16; s++) rk[s] = 0;
    int lbase = tid & ~3;
    #pragma unroll 4
    for (int o = 0; o < 64; o++) {
        unsigned long long ov = sB[(o >> 2)*128 + lbase + (o & 3)];
        #pragma unroll
        for (int e = 0; e < 16; e++) rk[e] += (ov < mine[e]) ? 1 : 0;
    }
    #pragma unroll
    for (int e = 0; e < 16; e++)
        if (rk[e] < 16)
            g_idx[(size_t)row*16 + rk[e]] = b*NN + (int)(mine[e] & 0x1FFFULL);
}

// ================= fused attention: 6 points/block, 192 threads, 2 blocks/SM =================
struct SmemA {
    float Wp2[4096], Wt1[4096], Wt2[4096];
    float U[PRS*PAD];     // relu(pos) -> then VPE (v + pos_enc)
    float Y[PRS*PAD];     // a_in -> relu -> scores (in-place)
    float Res[PTS*64];
    int   Idx[PRS];
};

// 4x8 tile; thread owns rows pg + 24*r (strided -> conflict-free x loads)
__device__ __forceinline__ void gemm4x8(const float* __restrict__ X, const float* __restrict__ W,
                                        int pg, int hg, float acc[4][8]) {
    #pragma unroll
    for (int r = 0; r < 4; r++)
        #pragma unroll
        for (int c = 0; c < 8; c++) acc[r][c] = 0.f;
    const float* wb = W + hg*8;
    #pragma unroll 2
    for (int i4 = 0; i4 < 16; i4++) {
        float xa[4][4];
        #pragma unroll
        for (int r = 0; r < 4; r++)
            *(float4*)xa[r] = *(const float4*)(X + (pg + 24*r)*PAD + i4*4);
        #pragma unroll
        for (int ii = 0; ii < 4; ii++) {
            int i = i4*4 + ii;
            float4 w0 = *(const float4*)(wb + i*64);
            float4 w1 = *(const float4*)(wb + i*64 + 4);
            float wv[8] = {w0.x, w0.y, w0.z, w0.w, w1.x, w1.y, w1.z, w1.w};
            #pragma unroll
            for (int r = 0; r < 4; r++)
                #pragma unroll
                for (int c = 0; c < 8; c++)
                    acc[r][c] = fmaf(xa[r][ii], wv[c], acc[r][c]);
        }
    }
}

__global__ __launch_bounds__(192, 2) void attn_kernel(
    const float* __restrict__ features,
    const float* __restrict__ bp1,
    const float* __restrict__ Wp2, const float* __restrict__ bp2,
    const float* __restrict__ Wt1, const float* __restrict__ bt1,
    const float* __restrict__ Wt2, const float* __restrict__ bt2,
    const float* __restrict__ Wa,  const float* __restrict__ ba,
    float* __restrict__ out) {
    extern __shared__ char smem_raw[];
    SmemA* sm = (SmemA*)smem_raw;
    int tid = threadIdx.x;        // 192
    int base = blockIdx.x * PTS;  // 6 points / block (last block partial)

    for (int i = tid; i < 1024; i += 192) {
        ((float4*)sm->Wp2)[i] = __ldg(((const float4*)Wp2) + i);
        ((float4*)sm->Wt1)[i] = __ldg(((const float4*)Wt1) + i);
        ((float4*)sm->Wt2)[i] = __ldg(((const float4*)Wt2) + i);
    }
    if (tid < PRS) {
        int prow = min(base + (tid >> 4), NP-1);
        sm->Idx[tid] = g_idx[(size_t)prow*16 + (tid & 15)];
    }
    __syncthreads();

    // ---- U[pair][i] = relu((A[n]+bp1) - A[j]) ----
    #pragma unroll
    for (int it = 0; it < 8; it++) {
        int flat = it*192 + tid;          // 0..1535
        int pair = flat >> 4, c4 = flat & 15;
        int prow = min(base + (pair >> 4), NP-1);
        int g = sm->Idx[pair];
        float4 an = __ldg(((const float4*)(g_A + (size_t)prow*64)) + c4);
        float4 bb = __ldg(((const float4*)bp1) + c4);
        float4 aj = __ldg(((const float4*)(g_A + (size_t)g*64)) + c4);
        float4 u;
        u.x = fmaxf(an.x + bb.x - aj.x, 0.f);
        u.y = fmaxf(an.y + bb.y - aj.y, 0.f);
        u.z = fmaxf(an.z + bb.z - aj.z, 0.f);
        u.w = fmaxf(an.w + bb.w - aj.w, 0.f);
        *(float4*)(sm->U + pair*PAD + c4*4) = u;
    }
    __syncthreads();

    int pg = tid >> 3;   // 0..23, rows pg + 24*r
    int hg = tid & 7;    // cols hg*8 .. +7
    float acc[4][8];

    // ---- GEMM1: pe = U @ Wp2 + bp2 ; Y = q - k + pe ; U := v + pe ----
    gemm4x8(sm->U, sm->Wp2, pg, hg, acc);
    __syncthreads();
    {
        float4 b0 = __ldg(((const float4*)bp2) + hg*2);
        float4 b1 = __ldg(((const float4*)bp2) + hg*2 + 1);
        float bb[8] = {b0.x, b0.y, b0.z, b0.w, b1.x, b1.y, b1.z, b1.w};
        #pragma unroll
        for (int r = 0; r < 4; r++) {
            int pair = pg + 24*r;
            int prow = min(base + (pair >> 4), NP-1);
            const float4* qp = (const float4*)(g_X + (size_t)prow*192) + hg*2;
            float4 q0 = __ldg(qp), q1 = __ldg(qp + 1);
            float qf[8] = {q0.x, q0.y, q0.z, q0.w, q1.x, q1.y, q1.z, q1.w};
            int g = sm->Idx[pair];
            const float4* kp = (const float4*)(g_X + (size_t)g*192 + 64) + hg*2;
            const float4* vp = (const float4*)(g_X + (size_t)g*192 + 128) + hg*2;
            float4 k0 = __ldg(kp), k1 = __ldg(kp + 1);
            float4 v0 = __ldg(vp), v1 = __ldg(vp + 1);
            float kf[8] = {k0.x, k0.y, k0.z, k0.w, k1.x, k1.y, k1.z, k1.w};
            float vf[8] = {v0.x, v0.y, v0.z, v0.w, v1.x, v1.y, v1.z, v1.w};
            float yv[8], uv[8];
            #pragma unroll
            for (int c = 0; c < 8; c++) {
                float pe = acc[r][c] + bb[c];
                yv[c] = qf[c] - kf[c] + pe;
                uv[c] = vf[c] + pe;
            }
            float* yb = sm->Y + pair*PAD + hg*8;
            float* ub = sm->U + pair*PAD + hg*8;
            *(float4*)yb       = make_float4(yv[0], yv[1], yv[2], yv[3]);
            *(float4*)(yb + 4) = make_float4(yv[4], yv[5], yv[6], yv[7]);
            *(float4*)ub       = make_float4(uv[0], uv[1], uv[2], uv[3]);
            *(float4*)(ub + 4) = make_float4(uv[4], uv[5], uv[6], uv[7]);
        }
    }
    __syncthreads();

    // ---- GEMM2: Y := relu(Y @ Wt1 + bt1) ----
    gemm4x8(sm->Y, sm->Wt1, pg, hg, acc);
    __syncthreads();
    {
        float4 b0 = __ldg(((const float4*)bt1) + hg*2);
        float4 b1 = __ldg(((const float4*)bt1) + hg*2 + 1);
        float bb[8] = {b0.x, b0.y, b0.z, b0.w, b1.x, b1.y, b1.z, b1.w};
        #pragma unroll
        for (int r = 0; r < 4; r++) {
            float* yb = sm->Y + (pg + 24*r)*PAD + hg*8;
            float t[8];
            #pragma unroll
            for (int c = 0; c < 8; c++) t[c] = fmaxf(acc[r][c] + bb[c], 0.f);
            *(float4*)yb       = make_float4(t[0], t[1], t[2], t[3]);
            *(float4*)(yb + 4) = make_float4(t[4], t[5], t[6], t[7]);
        }
    }
    __syncthreads();

    // ---- GEMM3: Y := (Y @ Wt2 + bt2) / 8 ----
    gemm4x8(sm->Y, sm->Wt2, pg, hg, acc);
    __syncthreads();
    {
        float4 b0 = __ldg(((const float4*)bt2) + hg*2);
        float4 b1 = __ldg(((const float4*)bt2) + hg*2 + 1);
        float bb[8] = {b0.x, b0.y, b0.z, b0.w, b1.x, b1.y, b1.z, b1.w};
        #pragma unroll
        for (int r = 0; r < 4; r++) {
            float* yb = sm->Y + (pg + 24*r)*PAD + hg*8;
            float t[8];
            #pragma unroll
            for (int c = 0; c < 8; c++) t[c] = (acc[r][c] + bb[c]) * 0.125f;
            *(float4*)yb       = make_float4(t[0], t[1], t[2], t[3]);
            *(float4*)(yb + 4) = make_float4(t[4], t[5], t[6], t[7]);
        }
    }
    __syncthreads();

    // ---- softmax over j + weighted sum with VPE ----
    #pragma unroll
    for (int e = tid; e < PTS*64; e += 192) {
        int p = e >> 6, h = e & 63;
        float m = -finf();
        #pragma unroll
        for (int j = 0; j < 16; j++)
            m = fmaxf(m, sm->Y[(p*16 + j)*PAD + h]);
        float num = 0.f, den = 0.f;
        #pragma unroll
        for (int j = 0; j < 16; j++) {
            float ex = __expf(sm->Y[(p*16 + j)*PAD + h] - m);
            den += ex;
            num = fmaf(ex, sm->U[(p*16 + j)*PAD + h], num);
        }
        sm->Res[p*64 + h] = num / den;
    }
    __syncthreads();

    // ---- final: out = Res @ Wa + ba + features ----
    #pragma unroll
    for (int e = tid; e < PTS*64; e += 192) {
        int p = e >> 6, h = e & 63;
        int row = base + p;
        if (row < NP) {
            float a = 0.f;
            const float* wa = Wa + h;
            #pragma unroll 8
            for (int i = 0; i < 64; i++)
                a = fmaf(sm->Res[p*64 + i], __ldg(wa + i*64), a);
            out[(size_t)row*64 + h] = a + __ldg(ba + h) + __ldg(features + (size_t)row*64 + h);
        }
    }
}

// ================= launch =================
extern "C" void kernel_launch(void* const* d_in, const int* in_sizes, int n_in,
                              void* d_out, int out_size) {
    const float* xyzp     = (const float*)d_in[0];
    const float* features = (const float*)d_in[1];
    const float* Wk  = (const float*)d_in[2];
    const float* bk  = (const float*)d_in[3];
    const float* Wq  = (const float*)d_in[4];
    const float* Wks = (const float*)d_in[5];
    const float* Wv  = (const float*)d_in[6];
    const float* Wp1 = (const float*)d_in[7];
    const float* bp1 = (const float*)d_in[8];
    const float* Wp2 = (const float*)d_in[9];
    const float* bp2 = (const float*)d_in[10];
    const float* Wt1 = (const float*)d_in[11];
    const float* bt1 = (const float*)d_in[12];
    const float* Wt2 = (const float*)d_in[13];
    const float* bt2 = (const float*)d_in[14];
    const float* Wa  = (const float*)d_in[15];
    const float* ba  = (const float*)d_in[16];
    float* out = (float*)d_out;

    cudaFuncSetAttribute(transform_kernel, cudaFuncAttributeMaxDynamicSharedMemorySize,
                         (int)sizeof(SmemT));
    cudaFuncSetAttribute(attn_kernel, cudaFuncAttributeMaxDynamicSharedMemorySize,
                         (int)sizeof(SmemA));

    fold_kernel<<<16, 256>>>(Wk, bk, Wq, Wks, Wv);
    transform_kernel<<<NP/16, 192, sizeof(SmemT)>>>(features, xyzp, Wp1);
    knn_kernel<<<512, 128>>>();
    int attn_grid = (NP + PTS - 1) / PTS;
    attn_kernel<<<attn_grid, 192, sizeof(SmemA)>>>(features, bp1, Wp2, bp2,
                                                   Wt1, bt1, Wt2, bt2, Wa, ba, out);
}